// round 1
// baseline (speedup 1.0000x reference)
#include <cuda_runtime.h>
#include <math.h>

// Problem constants (fixed by setup_inputs)
#define N_  4
#define A_  3
#define S_  13
#define NC  80
#define NM  32
#define G_  16
#define H_  104
#define W_  104
#define PC  (5 + NC + NM)   // 117
#define HW  (H_ * W_)       // 10816
#define NCELL (N_ * A_ * S_ * S_)  // 2028

struct Acc {
    double noobj_sum;
    double obj_sum;
    double giou1m_sum;   // sum of (1 - giou) over obj
    double xy_sum;
    double wh_sum;
    double cls_sum;
    double seg_sum;      // sum of region_sum/area over valid
    double n_obj;
    double n_noobj;
    double n_valid;
};

__device__ Acc g_acc;

__global__ void zero_acc_kernel() {
    if (threadIdx.x == 0) {
        g_acc.noobj_sum = 0.0; g_acc.obj_sum = 0.0; g_acc.giou1m_sum = 0.0;
        g_acc.xy_sum = 0.0;    g_acc.wh_sum = 0.0; g_acc.cls_sum = 0.0;
        g_acc.seg_sum = 0.0;   g_acc.n_obj = 0.0;  g_acc.n_noobj = 0.0;
        g_acc.n_valid = 0.0;
    }
}

__device__ __forceinline__ float bce_logits(float x, float z) {
    // max(x,0) - x*z + log1p(exp(-|x|))
    return fmaxf(x, 0.0f) - x * z + log1pf(expf(-fabsf(x)));
}

__global__ void __launch_bounds__(128)
cell_kernel(const float* __restrict__ preds,
            const float* __restrict__ target,
            const float* __restrict__ anchors,
            const float* __restrict__ proto,
            const float* __restrict__ masks)
{
    const int c   = blockIdx.x;
    const int tid = threadIdx.x;

    const float* t = target + (size_t)c * 7;
    const float* p = preds  + (size_t)c * PC;

    const float conf_t = t[4];
    const bool  obj    = (conf_t == 1.0f);

    if (!obj) {
        if (tid == 0 && conf_t == 0.0f) {
            atomicAdd(&g_acc.noobj_sum, (double)bce_logits(p[4], 0.0f));
            atomicAdd(&g_acc.n_noobj, 1.0);
        }
        return;
    }

    // decode (n, a, i, j)
    const int n   = c / (A_ * S_ * S_);
    const int rem = c % (A_ * S_ * S_);
    const int a   = rem / (S_ * S_);
    const int ij  = rem % (S_ * S_);
    const int i   = ij / S_;
    const int j   = ij % S_;

    __shared__ float tc[NM];
    __shared__ float red[128];
    __shared__ int   sh_y1, sh_ny, sh_x1, sh_nx, sh_area, sh_id;

    // ---- per-cell scalar losses + region bounds (thread 0) ----
    if (tid == 0) {
        atomicAdd(&g_acc.n_obj, 1.0);

        const float confl = p[4];
        const float anw = anchors[a * 2 + 0];
        const float anh = anchors[a * 2 + 1];

        const float sx = 1.0f / (1.0f + expf(-p[0]));
        const float sy = 1.0f / (1.0f + expf(-p[1]));
        const float pw = expf(p[2]) * anw;
        const float ph = expf(p[3]) * anh;

        const float tx = t[0], ty = t[1], tw = t[2], th = t[3];

        // GIoU(pred_box=[sx,sy,pw,ph], tgt=[tx,ty,tw,th])
        const float eps = 1e-9f;
        const float b1x1 = sx - pw * 0.5f, b1y1 = sy - ph * 0.5f;
        const float b1x2 = sx + pw * 0.5f, b1y2 = sy + ph * 0.5f;
        const float b2x1 = tx - tw * 0.5f, b2y1 = ty - th * 0.5f;
        const float b2x2 = tx + tw * 0.5f, b2y2 = ty + th * 0.5f;
        const float a1 = fmaxf(b1x2 - b1x1, 0.0f) * fmaxf(b1y2 - b1y1, 0.0f) + eps;
        const float a2 = fmaxf(b2x2 - b2x1, 0.0f) * fmaxf(b2y2 - b2y1, 0.0f) + eps;
        const float iw = fmaxf(fminf(b1x2, b2x2) - fmaxf(b1x1, b2x1), 0.0f);
        const float ih = fmaxf(fminf(b1y2, b2y2) - fmaxf(b1y1, b2y1), 0.0f);
        const float inter = iw * ih + eps;
        const float uni   = a1 + a2 - inter + eps;
        const float iou   = inter / uni;
        const float cw = fmaxf(b1x2, b2x2) - fminf(b1x1, b2x1);
        const float ch = fmaxf(b1y2, b2y2) - fminf(b1y1, b2y1);
        const float carea = cw * ch + eps;
        const float giou  = iou - (carea - uni) / carea;

        atomicAdd(&g_acc.giou1m_sum, (double)(1.0f - giou));

        const float obj_tgt = conf_t * fmaxf(giou, 0.0f);
        atomicAdd(&g_acc.obj_sum, (double)bce_logits(confl, obj_tgt));

        atomicAdd(&g_acc.xy_sum, (double)(bce_logits(sx, tx) + bce_logits(sy, ty)));

        const float twx = logf(1e-16f + tw / anw);
        const float twy = logf(1e-16f + th / anh);
        const float dw = p[2] - twx, dh = p[3] - twy;
        atomicAdd(&g_acc.wh_sum, (double)(dw * dw + dh * dh));

        // class NLL via log-softmax over NC
        float mx = -3.4e38f;
        for (int k = 0; k < NC; k++) mx = fmaxf(mx, p[5 + k]);
        float se = 0.0f;
        for (int k = 0; k < NC; k++) se += expf(p[5 + k] - mx);
        const int lab = (int)t[5];
        const float logp = p[5 + lab] - mx - logf(se);
        atomicAdd(&g_acc.cls_sum, (double)(-logp));

        // segment region bounds
        const float bx = (tx + (float)j) / (float)S_ * (float)W_;
        const float by = (ty + (float)i) / (float)S_ * (float)H_;
        const float bw = tw / (float)S_ * (float)W_;
        const float bh = th / (float)S_ * (float)H_;
        const int x1 = (int)floorf(bx - bw * 0.5f);
        const int x2 = (int)floorf(bx + bw * 0.5f);
        const int y1 = (int)floorf(by - bh * 0.5f);
        const int y2 = (int)floorf(by + bh * 0.5f);
        const int yl = max(y1, 0), yh = min(y2, H_);
        const int xl = max(x1, 0), xh = min(x2, W_);
        const int nrows = max(0, yh - yl);
        const int ncols = max(0, xh - xl);
        sh_y1 = yl; sh_ny = nrows;
        sh_x1 = xl; sh_nx = ncols;
        sh_area = nrows * ncols;
        int id = (int)t[6];
        id = min(max(id, 0), G_ - 1);
        sh_id = id;
        if (sh_area > 0) atomicAdd(&g_acc.n_valid, 1.0);
    }

    // coeffs: tanh of 32 mask coefficients
    if (tid < NM) tc[tid] = tanhf(p[5 + NC + tid]);
    __syncthreads();

    const int area = sh_area;
    if (area <= 0) return;

    const float* __restrict__ pr = proto + (size_t)n * NM * HW;
    const float* __restrict__ tm = masks + ((size_t)n * G_ + sh_id) * HW;

    const int npix = sh_ny * sh_nx;
    const int nx   = sh_nx;
    float acc = 0.0f;
    for (int pix = tid; pix < npix; pix += 128) {
        const int r  = pix / nx;
        const int cc = pix - r * nx;
        const int h  = sh_y1 + r;
        const int w  = sh_x1 + cc;
        const int off = h * W_ + w;
        float dot = 0.0f;
        #pragma unroll
        for (int m = 0; m < NM; m++)
            dot = fmaf(tc[m], pr[m * HW + off], dot);
        acc += bce_logits(dot, tm[off]);
    }
    red[tid] = acc;
    __syncthreads();
    #pragma unroll
    for (int s = 64; s > 0; s >>= 1) {
        if (tid < s) red[tid] += red[tid + s];
        __syncthreads();
    }
    if (tid == 0) {
        atomicAdd(&g_acc.seg_sum, (double)(red[0] / (float)area));
    }
}

__global__ void finalize_kernel(float* __restrict__ out) {
    if (threadIdx.x != 0 || blockIdx.x != 0) return;
    const Acc acc = g_acc;
    const double eps = 1e-9;
    const double noobj_loss = acc.noobj_sum / acc.n_noobj;
    const double obj_loss   = acc.obj_sum   / acc.n_obj;
    const double xy_bce     = acc.xy_sum    / (acc.n_obj * 2.0);
    const double wh_mse     = acc.wh_sum    / (acc.n_obj * 2.0);
    const double box_loss   = xy_bce + wh_mse + acc.giou1m_sum / acc.n_obj;
    const double class_loss = acc.cls_sum   / acc.n_obj;
    const double seg_loss   = acc.seg_sum   / (acc.n_valid + eps);

    const double box_l   = 8.0  * box_loss;
    const double obj_l   = 2.0  * obj_loss;
    const double noobj_l = 4.0  * noobj_loss;
    const double cls_l   = 1.0  * class_loss;
    const double seg_l   = 10.0 * seg_loss;

    out[0] = (float)box_l;
    out[1] = (float)obj_l;
    out[2] = (float)noobj_l;
    out[3] = (float)cls_l;
    out[4] = (float)seg_l;
    out[5] = (float)(box_l + obj_l + noobj_l + cls_l + seg_l);
}

extern "C" void kernel_launch(void* const* d_in, const int* in_sizes, int n_in,
                              void* d_out, int out_size)
{
    const float* preds   = (const float*)d_in[0];
    const float* target  = (const float*)d_in[1];
    const float* anchors = (const float*)d_in[2];
    const float* proto   = (const float*)d_in[3];
    const float* masks   = (const float*)d_in[4];
    float* out = (float*)d_out;

    zero_acc_kernel<<<1, 32>>>();
    cell_kernel<<<NCELL, 128>>>(preds, target, anchors, proto, masks);
    finalize_kernel<<<1, 32>>>(out);
}